// round 9
// baseline (speedup 1.0000x reference)
#include <cuda_runtime.h>

// Problem constants (fixed by the reference)
#define HID 4096
#define EMB 4096
#define VOC 4096
#define LEN 2048

// ---------------- scratch (device globals; no allocations allowed) ---------
__device__ float g_attn_logits[LEN];      // 2048
__device__ float g_ctx_part[64 * HID];    // 64 L-chunks x 4096 partials
__device__ float g_ctx[HID];              // attention context
__device__ float g_x[HID];                // lstm input
__device__ float g_gates[4 * HID];        // 16384
__device__ float g_hnew[HID];
__device__ float g_logits[VOC];

// ---------------- helpers --------------------------------------------------
__device__ __forceinline__ float block_reduce_sum(float v) {
    __shared__ float s[32];
    int lane = threadIdx.x & 31, wid = threadIdx.x >> 5;
    #pragma unroll
    for (int o = 16; o; o >>= 1) v += __shfl_down_sync(0xffffffffu, v, o);
    if (lane == 0) s[wid] = v;
    __syncthreads();
    int nw = blockDim.x >> 5;
    v = (threadIdx.x < nw) ? s[threadIdx.x] : 0.0f;
    if (wid == 0) {
        #pragma unroll
        for (int o = 16; o; o >>= 1) v += __shfl_down_sync(0xffffffffu, v, o);
    }
    return v;  // valid in thread 0
}

// Reduce R per-thread accumulators across a 256-thread (8-warp) block.
// Thread r<R ends with total[r] in acc[0]. Deterministic order.
template <int R>
__device__ __forceinline__ void block_reduce_sumR(float acc[R], volatile float* s /*[R*8]*/) {
    int lane = threadIdx.x & 31, wid = threadIdx.x >> 5;
    #pragma unroll
    for (int r = 0; r < R; ++r) {
        float v = acc[r];
        #pragma unroll
        for (int o = 16; o; o >>= 1) v += __shfl_down_sync(0xffffffffu, v, o);
        if (lane == 0) s[r * 8 + wid] = v;
    }
    __syncthreads();
    if (threadIdx.x < R) {
        float t = 0.0f;
        #pragma unroll
        for (int w = 0; w < 8; ++w) t += s[threadIdx.x * 8 + w];
        acc[0] = t;   // result for row threadIdx.x
    }
}

__device__ __forceinline__ float4 ldcs4(const float4* p) {
    return __ldcs(p);   // streaming: single-use data, evict-first
}

__device__ __forceinline__ float dot4(float4 a, float4 b) {
    return a.x * b.x + a.y * b.y + a.z * b.z + a.w * b.w;
}

// ---------------- kernels --------------------------------------------------

// ROWS-per-block concat GEMV:
// y[row] = act( dot(W[row,0:E], emb[token]) + dot(W[row,E:E+H], xb) + b[row] )
template <int RELU, int ROWS>
__global__ void __launch_bounds__(256) k_gemv_cat(const float* __restrict__ W,
                       const int* __restrict__ token,
                       const float* __restrict__ emb,
                       const float* __restrict__ xb,
                       const float* __restrict__ b,
                       float* __restrict__ y) {
    __shared__ float s[ROWS * 8];
    int row0 = blockIdx.x * ROWS;
    const float4* W0 = reinterpret_cast<const float4*>(W + (size_t)row0 * (EMB + HID));
    const size_t RS = (EMB + HID) / 4;   // row stride in float4
    const float4* ea = reinterpret_cast<const float4*>(emb + (size_t)token[0] * EMB);
    const float4* xv = reinterpret_cast<const float4*>(xb);
    float acc[ROWS];
    #pragma unroll
    for (int r = 0; r < ROWS; ++r) acc[r] = 0.0f;
    #pragma unroll
    for (int k = 0; k < EMB / 4; k += 256) {
        int i = k + threadIdx.x;
        float4 v = __ldg(ea + i);
        #pragma unroll
        for (int r = 0; r < ROWS; ++r) acc[r] += dot4(ldcs4(W0 + (size_t)r * RS + i), v);
    }
    #pragma unroll
    for (int k = 0; k < HID / 4; k += 256) {
        int i = k + threadIdx.x;
        float4 v = xv[i];
        #pragma unroll
        for (int r = 0; r < ROWS; ++r) acc[r] += dot4(ldcs4(W0 + (size_t)r * RS + (EMB / 4) + i), v);
    }
    block_reduce_sumR<ROWS>(acc, s);
    if (threadIdx.x < ROWS) {
        float r = acc[0] + b[row0 + threadIdx.x];
        if (RELU) r = fmaxf(r, 0.0f);
        y[row0 + threadIdx.x] = r;
    }
}

// ROWS-per-block plain GEMV: y[row] = dot(W[row,:], x) + b[row]
template <int NCOLS, int ROWS>
__global__ void __launch_bounds__(256) k_gemv(const float* __restrict__ W,
                       const float* __restrict__ x,
                       const float* __restrict__ b,
                       float* __restrict__ y) {
    __shared__ float s[ROWS * 8];
    int row0 = blockIdx.x * ROWS;
    const float4* W0 = reinterpret_cast<const float4*>(W + (size_t)row0 * NCOLS);
    const size_t RS = NCOLS / 4;
    const float4* xv = reinterpret_cast<const float4*>(x);
    float acc[ROWS];
    #pragma unroll
    for (int r = 0; r < ROWS; ++r) acc[r] = 0.0f;
    #pragma unroll
    for (int k = 0; k < NCOLS / 4; k += 256) {
        int i = k + threadIdx.x;
        float4 v = xv[i];
        #pragma unroll
        for (int r = 0; r < ROWS; ++r) acc[r] += dot4(ldcs4(W0 + (size_t)r * RS + i), v);
    }
    block_reduce_sumR<ROWS>(acc, s);
    if (threadIdx.x < ROWS) {
        y[row0 + threadIdx.x] = acc[0] + b[row0 + threadIdx.x];
    }
}

// ctx partials WITH fused redundant softmax.
// grid (4 j-chunks, 64 l-chunks) = 256 blocks, 256 thr; thread = one float4 col.
// Every block deterministically re-reduces the 2048 logits (L2-hot, 8KB) to
// (max, sum); all blocks get bit-identical results. The block's 32 attention
// weights are computed ONCE into shared memory and the encoder loop reads
// them via broadcast LDS — no expf in the inner loop.
__global__ void __launch_bounds__(256) k_ctx_partial(const float* __restrict__ enc,
                                                     float* __restrict__ out_attn) {
    __shared__ float s_max, s_sum;
    __shared__ float sm[32];
    __shared__ float sw[32];          // this block's 32 attention weights
    int t = threadIdx.x, lane = t & 31, wid = t >> 5;

    // --- softmax statistics over all 2048 logits (8 per thread) ---
    float lv[8];
    #pragma unroll
    for (int k = 0; k < 8; ++k) lv[k] = g_attn_logits[t + 256 * k];
    float m = lv[0];
    #pragma unroll
    for (int k = 1; k < 8; ++k) m = fmaxf(m, lv[k]);
    #pragma unroll
    for (int o = 16; o; o >>= 1) m = fmaxf(m, __shfl_down_sync(0xffffffffu, m, o));
    if (lane == 0) sm[wid] = m;
    __syncthreads();
    if (wid == 0) {
        float v = (lane < 8) ? sm[lane] : -3.402823466e38f;
        #pragma unroll
        for (int o = 4; o; o >>= 1) v = fmaxf(v, __shfl_down_sync(0xffffffffu, v, o));
        if (lane == 0) s_max = v;
    }
    __syncthreads();
    float mx = s_max;
    float esum = 0.0f;
    #pragma unroll
    for (int k = 0; k < 8; ++k) esum += expf(lv[k] - mx);
    float ssum = block_reduce_sum(esum);
    if (t == 0) s_sum = ssum;
    __syncthreads();
    float inv = 1.0f / s_sum;

    int jc = blockIdx.x, lc = blockIdx.y;
    int l0 = lc * 32;

    // --- compute this block's 32 weights once into shared ---
    if (t < 32) {
        float w = expf(g_attn_logits[l0 + t] - mx) * inv;
        sw[t] = w;
        if (jc == 0) out_attn[l0 + t] = w;   // attn_w slice to output tail
    }
    __syncthreads();

    // --- weighted encoder reduction over this block's 32 L-rows ---
    int j4 = jc * 256 + t;                    // float4 column index 0..1023
    const float4* enc4 = reinterpret_cast<const float4*>(enc);
    float4 acc = make_float4(0.f, 0.f, 0.f, 0.f);
    #pragma unroll 8
    for (int l = 0; l < 32; ++l) {
        float w = sw[l];                      // broadcast LDS
        float4 v = ldcs4(enc4 + (size_t)(l0 + l) * (HID / 4) + j4);
        acc.x += w * v.x; acc.y += w * v.y; acc.z += w * v.z; acc.w += w * v.w;
    }
    reinterpret_cast<float4*>(g_ctx_part)[(size_t)lc * (HID / 4) + j4] = acc;
}

// ctx reduce (64 partials) into g_ctx
__global__ void __launch_bounds__(256) k_ctx_reduce() {
    int j4 = blockIdx.x * blockDim.x + threadIdx.x;   // 0..1023
    const float4* p4 = reinterpret_cast<const float4*>(g_ctx_part);
    float4 acc = make_float4(0.f, 0.f, 0.f, 0.f);
    #pragma unroll
    for (int lc = 0; lc < 64; ++lc) {
        float4 v = p4[(size_t)lc * (HID / 4) + j4];
        acc.x += v.x; acc.y += v.y; acc.z += v.z; acc.w += v.w;
    }
    reinterpret_cast<float4*>(g_ctx)[j4] = acc;
}

// gates: 8 rows per block (2048 blocks): dot(W_ih[r],x)+dot(W_hh[r],h)+b
__global__ void __launch_bounds__(256) k_gates8(const float* __restrict__ Wih,
                        const float* __restrict__ Whh,
                        const float* __restrict__ h,
                        const float* __restrict__ bih,
                        const float* __restrict__ bhh) {
    __shared__ float s[8 * 8];
    int row0 = blockIdx.x * 8;
    const float4* wi0 = reinterpret_cast<const float4*>(Wih + (size_t)row0 * HID);
    const float4* wh0 = reinterpret_cast<const float4*>(Whh + (size_t)row0 * HID);
    const size_t RS = HID / 4;
    const float4* xv = reinterpret_cast<const float4*>(g_x);
    const float4* hv = reinterpret_cast<const float4*>(h);
    float acc[8] = {0.f, 0.f, 0.f, 0.f, 0.f, 0.f, 0.f, 0.f};
    #pragma unroll
    for (int k = 0; k < HID / 4; k += 256) {
        int i = k + threadIdx.x;
        float4 v = xv[i];
        float4 u = hv[i];
        #pragma unroll
        for (int r = 0; r < 8; ++r) {
            acc[r] += dot4(ldcs4(wi0 + (size_t)r * RS + i), v);
            acc[r] += dot4(ldcs4(wh0 + (size_t)r * RS + i), u);
        }
    }
    block_reduce_sumR<8>(acc, s);
    if (threadIdx.x < 8) {
        int row = row0 + threadIdx.x;
        g_gates[row] = acc[0] + bih[row] + bhh[row];
    }
}

// LSTM cell elementwise; writes h_new/c_new to out and g_hnew
__device__ __forceinline__ float sigm(float v) { return 1.0f / (1.0f + expf(-v)); }
__global__ void __launch_bounds__(256) k_cell(const float* __restrict__ c, float* __restrict__ out) {
    int j = blockIdx.x * blockDim.x + threadIdx.x;
    if (j >= HID) return;
    float ig = g_gates[j];
    float fg = g_gates[HID + j];
    float gg = g_gates[2 * HID + j];
    float og = g_gates[3 * HID + j];
    float cn = sigm(fg) * c[j] + sigm(ig) * tanhf(gg);
    float hn = sigm(og) * tanhf(cn);
    g_hnew[j] = hn;
    out[4096 + j] = hn;      // h_new
    out[8192 + j] = cn;      // c_new
}

// log_softmax over 4096 logits -> out[0:4096]
__global__ void __launch_bounds__(1024) k_logsoftmax(float* __restrict__ out) {
    int t = threadIdx.x;                 // 1024 threads, 4 elems each
    float v0 = g_logits[t], v1 = g_logits[t + 1024],
          v2 = g_logits[t + 2048], v3 = g_logits[t + 3072];
    float m = fmaxf(fmaxf(v0, v1), fmaxf(v2, v3));
    __shared__ float sm[32];
    __shared__ float s_max, s_sum;
    int lane = t & 31, wid = t >> 5;
    #pragma unroll
    for (int o = 16; o; o >>= 1) m = fmaxf(m, __shfl_down_sync(0xffffffffu, m, o));
    if (lane == 0) sm[wid] = m;
    __syncthreads();
    if (wid == 0) {
        float v = sm[lane];
        #pragma unroll
        for (int o = 16; o; o >>= 1) v = fmaxf(v, __shfl_down_sync(0xffffffffu, v, o));
        if (lane == 0) s_max = v;
    }
    __syncthreads();
    float mx = s_max;
    float e0 = expf(v0 - mx), e1 = expf(v1 - mx), e2 = expf(v2 - mx), e3 = expf(v3 - mx);
    float ssum = block_reduce_sum(e0 + e1 + e2 + e3);
    if (t == 0) s_sum = ssum;
    __syncthreads();
    float lse = mx + logf(s_sum);
    out[t]        = v0 - lse;
    out[t + 1024] = v1 - lse;
    out[t + 2048] = v2 - lse;
    out[t + 3072] = v3 - lse;
}

// ---------------- launch ----------------------------------------------------
extern "C" void kernel_launch(void* const* d_in, const int* in_sizes, int n_in,
                              void* d_out, int out_size) {
    const int*   token = (const int*)  d_in[0];
    const float* h     = (const float*)d_in[1];
    const float* c     = (const float*)d_in[2];
    const float* enc   = (const float*)d_in[3];
    const float* emb   = (const float*)d_in[4];
    const float* Wattn = (const float*)d_in[5];
    const float* battn = (const float*)d_in[6];
    const float* Wcomb = (const float*)d_in[7];
    const float* bcomb = (const float*)d_in[8];
    const float* Wih   = (const float*)d_in[9];
    const float* Whh   = (const float*)d_in[10];
    const float* bih   = (const float*)d_in[11];
    const float* bhh   = (const float*)d_in[12];
    const float* Wout  = (const float*)d_in[13];
    const float* bout  = (const float*)d_in[14];
    float* out = (float*)d_out;

    float *d_attn_logits, *d_ctx, *d_x, *d_hnew, *d_logits;
    cudaGetSymbolAddress((void**)&d_attn_logits, g_attn_logits);
    cudaGetSymbolAddress((void**)&d_ctx,  g_ctx);
    cudaGetSymbolAddress((void**)&d_x,    g_x);
    cudaGetSymbolAddress((void**)&d_hnew, g_hnew);
    cudaGetSymbolAddress((void**)&d_logits, g_logits);

    // 1) attention logits: W_attn @ [emb[token], h]  (2048 rows x 8192 cols)
    k_gemv_cat<0, 8><<<LEN / 8, 256>>>(Wattn, token, emb, h, battn, d_attn_logits);
    // 2) fused softmax + ctx partials (+ attn_w to output tail at 12288)
    k_ctx_partial<<<dim3(4, 64), 256>>>(enc, out + 12288);
    k_ctx_reduce<<<4, 256>>>();
    // 3) x = relu(W_comb @ [emb[token], ctx] + b)
    k_gemv_cat<1, 8><<<HID / 8, 256>>>(Wcomb, token, emb, d_ctx, bcomb, d_x);
    // 4) gates = W_ih@x + W_hh@h + b_ih + b_hh
    k_gates8<<<4 * HID / 8, 256>>>(Wih, Whh, h, bih, bhh);
    // 5) LSTM cell -> h_new, c_new
    k_cell<<<HID / 256, 256>>>(c, out);
    // 6) logits = W_out @ h_new + b_out
    k_gemv<HID, 8><<<VOC / 8, 256>>>(Wout, d_hnew, bout, d_logits);
    // 7) log_softmax -> out[0:4096]
    k_logsoftmax<<<1, 1024>>>(out);
}

// round 12
// speedup vs baseline: 1.0167x; 1.0167x over previous
#include <cuda_runtime.h>

// Problem constants (fixed by the reference)
#define HID 4096
#define EMB 4096
#define VOC 4096
#define LEN 2048

// ---------------- scratch (device globals; no allocations allowed) ---------
__device__ float g_attn_logits[LEN];      // 2048
__device__ float g_ctx_part[128 * HID];   // 128 L-chunks x 4096 partials
__device__ float g_ctx[HID];              // attention context
__device__ float g_x[HID];                // lstm input
__device__ float g_gates[4 * HID];        // 16384
__device__ float g_hnew[HID];
__device__ float g_logits[VOC];

// ---------------- helpers --------------------------------------------------
__device__ __forceinline__ float block_reduce_sum(float v) {
    __shared__ float s[32];
    int lane = threadIdx.x & 31, wid = threadIdx.x >> 5;
    #pragma unroll
    for (int o = 16; o; o >>= 1) v += __shfl_down_sync(0xffffffffu, v, o);
    if (lane == 0) s[wid] = v;
    __syncthreads();
    int nw = blockDim.x >> 5;
    v = (threadIdx.x < nw) ? s[threadIdx.x] : 0.0f;
    if (wid == 0) {
        #pragma unroll
        for (int o = 16; o; o >>= 1) v += __shfl_down_sync(0xffffffffu, v, o);
    }
    return v;  // valid in thread 0
}

// Reduce R per-thread accumulators across a 256-thread (8-warp) block.
// Thread r<R ends with total[r] in acc[0]. Deterministic order.
template <int R>
__device__ __forceinline__ void block_reduce_sumR(float acc[R], volatile float* s /*[R*8]*/) {
    int lane = threadIdx.x & 31, wid = threadIdx.x >> 5;
    #pragma unroll
    for (int r = 0; r < R; ++r) {
        float v = acc[r];
        #pragma unroll
        for (int o = 16; o; o >>= 1) v += __shfl_down_sync(0xffffffffu, v, o);
        if (lane == 0) s[r * 8 + wid] = v;
    }
    __syncthreads();
    if (threadIdx.x < R) {
        float t = 0.0f;
        #pragma unroll
        for (int w = 0; w < 8; ++w) t += s[threadIdx.x * 8 + w];
        acc[0] = t;   // result for row threadIdx.x
    }
}

__device__ __forceinline__ float4 ldcs4(const float4* p) {
    return __ldcs(p);   // streaming: single-use data, evict-first
}

__device__ __forceinline__ float dot4(float4 a, float4 b) {
    return a.x * b.x + a.y * b.y + a.z * b.z + a.w * b.w;
}

// ---------------- kernels --------------------------------------------------

// ROWS-per-block concat GEMV:
// y[row] = act( dot(W[row,0:E], emb[token]) + dot(W[row,E:E+H], xb) + b[row] )
// Grid sized for >=6 resident blocks/SM; launch_bounds caps regs at 42.
template <int RELU, int ROWS>
__global__ void __launch_bounds__(256, 6) k_gemv_cat(const float* __restrict__ W,
                       const int* __restrict__ token,
                       const float* __restrict__ emb,
                       const float* __restrict__ xb,
                       const float* __restrict__ b,
                       float* __restrict__ y) {
    __shared__ float s[ROWS * 8];
    int row0 = blockIdx.x * ROWS;
    const float4* W0 = reinterpret_cast<const float4*>(W + (size_t)row0 * (EMB + HID));
    const size_t RS = (EMB + HID) / 4;   // row stride in float4
    const float4* ea = reinterpret_cast<const float4*>(emb + (size_t)token[0] * EMB);
    const float4* xv = reinterpret_cast<const float4*>(xb);
    float acc[ROWS];
    #pragma unroll
    for (int r = 0; r < ROWS; ++r) acc[r] = 0.0f;
    #pragma unroll
    for (int k = 0; k < EMB / 4; k += 256) {
        int i = k + threadIdx.x;
        float4 v = __ldg(ea + i);
        #pragma unroll
        for (int r = 0; r < ROWS; ++r) acc[r] += dot4(ldcs4(W0 + (size_t)r * RS + i), v);
    }
    #pragma unroll
    for (int k = 0; k < HID / 4; k += 256) {
        int i = k + threadIdx.x;
        float4 v = xv[i];
        #pragma unroll
        for (int r = 0; r < ROWS; ++r) acc[r] += dot4(ldcs4(W0 + (size_t)r * RS + (EMB / 4) + i), v);
    }
    block_reduce_sumR<ROWS>(acc, s);
    if (threadIdx.x < ROWS) {
        float r = acc[0] + b[row0 + threadIdx.x];
        if (RELU) r = fmaxf(r, 0.0f);
        y[row0 + threadIdx.x] = r;
    }
}

// ROWS-per-block plain GEMV: y[row] = dot(W[row,:], x) + b[row]
template <int NCOLS, int ROWS>
__global__ void __launch_bounds__(256, 6) k_gemv(const float* __restrict__ W,
                       const float* __restrict__ x,
                       const float* __restrict__ b,
                       float* __restrict__ y) {
    __shared__ float s[ROWS * 8];
    int row0 = blockIdx.x * ROWS;
    const float4* W0 = reinterpret_cast<const float4*>(W + (size_t)row0 * NCOLS);
    const size_t RS = NCOLS / 4;
    const float4* xv = reinterpret_cast<const float4*>(x);
    float acc[ROWS];
    #pragma unroll
    for (int r = 0; r < ROWS; ++r) acc[r] = 0.0f;
    #pragma unroll
    for (int k = 0; k < NCOLS / 4; k += 256) {
        int i = k + threadIdx.x;
        float4 v = xv[i];
        #pragma unroll
        for (int r = 0; r < ROWS; ++r) acc[r] += dot4(ldcs4(W0 + (size_t)r * RS + i), v);
    }
    block_reduce_sumR<ROWS>(acc, s);
    if (threadIdx.x < ROWS) {
        y[row0 + threadIdx.x] = acc[0] + b[row0 + threadIdx.x];
    }
}

// ctx partials WITH fused redundant softmax.
// grid (4 j-chunks, 128 l-chunks) = 512 blocks, 256 thr; thread = one float4 col.
// Every block deterministically re-reduces the 2048 logits (L2-hot, 8KB) to
// (max, sum); all blocks get bit-identical results. The block's 16 attention
// weights are computed ONCE into shared memory; encoder loop reads them via
// broadcast LDS — no expf in the inner loop.
__global__ void __launch_bounds__(256) k_ctx_partial(const float* __restrict__ enc,
                                                     float* __restrict__ out_attn) {
    __shared__ float s_max, s_sum;
    __shared__ float sm[32];
    __shared__ float sw[16];          // this block's 16 attention weights
    int t = threadIdx.x, lane = t & 31, wid = t >> 5;

    // --- softmax statistics over all 2048 logits (8 per thread) ---
    float lv[8];
    #pragma unroll
    for (int k = 0; k < 8; ++k) lv[k] = g_attn_logits[t + 256 * k];
    float m = lv[0];
    #pragma unroll
    for (int k = 1; k < 8; ++k) m = fmaxf(m, lv[k]);
    #pragma unroll
    for (int o = 16; o; o >>= 1) m = fmaxf(m, __shfl_down_sync(0xffffffffu, m, o));
    if (lane == 0) sm[wid] = m;
    __syncthreads();
    if (wid == 0) {
        float v = (lane < 8) ? sm[lane] : -3.402823466e38f;
        #pragma unroll
        for (int o = 4; o; o >>= 1) v = fmaxf(v, __shfl_down_sync(0xffffffffu, v, o));
        if (lane == 0) s_max = v;
    }
    __syncthreads();
    float mx = s_max;
    float esum = 0.0f;
    #pragma unroll
    for (int k = 0; k < 8; ++k) esum += expf(lv[k] - mx);
    float ssum = block_reduce_sum(esum);
    if (t == 0) s_sum = ssum;
    __syncthreads();
    float inv = 1.0f / s_sum;

    int jc = blockIdx.x, lc = blockIdx.y;
    int l0 = lc * 16;

    // --- compute this block's 16 weights once into shared ---
    if (t < 16) {
        float w = expf(g_attn_logits[l0 + t] - mx) * inv;
        sw[t] = w;
        if (jc == 0) out_attn[l0 + t] = w;   // attn_w slice to output tail
    }
    __syncthreads();

    // --- weighted encoder reduction over this block's 16 L-rows ---
    int j4 = jc * 256 + t;                    // float4 column index 0..1023
    const float4* enc4 = reinterpret_cast<const float4*>(enc);
    float4 acc = make_float4(0.f, 0.f, 0.f, 0.f);
    #pragma unroll
    for (int l = 0; l < 16; ++l) {
        float w = sw[l];                      // broadcast LDS
        float4 v = ldcs4(enc4 + (size_t)(l0 + l) * (HID / 4) + j4);
        acc.x += w * v.x; acc.y += w * v.y; acc.z += w * v.z; acc.w += w * v.w;
    }
    reinterpret_cast<float4*>(g_ctx_part)[(size_t)lc * (HID / 4) + j4] = acc;
}

// ctx reduce (128 partials) into g_ctx — float granularity, 16 blocks x 256 thr
__global__ void __launch_bounds__(256) k_ctx_reduce() {
    int j = blockIdx.x * blockDim.x + threadIdx.x;    // 0..4095
    float acc = 0.0f;
    #pragma unroll 16
    for (int lc = 0; lc < 128; ++lc) {
        acc += g_ctx_part[(size_t)lc * HID + j];
    }
    g_ctx[j] = acc;
}

// gates: 8 rows per block (2048 blocks): dot(W_ih[r],x)+dot(W_hh[r],h)+b
__global__ void __launch_bounds__(256) k_gates8(const float* __restrict__ Wih,
                        const float* __restrict__ Whh,
                        const float* __restrict__ h,
                        const float* __restrict__ bih,
                        const float* __restrict__ bhh) {
    __shared__ float s[8 * 8];
    int row0 = blockIdx.x * 8;
    const float4* wi0 = reinterpret_cast<const float4*>(Wih + (size_t)row0 * HID);
    const float4* wh0 = reinterpret_cast<const float4*>(Whh + (size_t)row0 * HID);
    const size_t RS = HID / 4;
    const float4* xv = reinterpret_cast<const float4*>(g_x);
    const float4* hv = reinterpret_cast<const float4*>(h);
    float acc[8] = {0.f, 0.f, 0.f, 0.f, 0.f, 0.f, 0.f, 0.f};
    #pragma unroll
    for (int k = 0; k < HID / 4; k += 256) {
        int i = k + threadIdx.x;
        float4 v = xv[i];
        float4 u = hv[i];
        #pragma unroll
        for (int r = 0; r < 8; ++r) {
            acc[r] += dot4(ldcs4(wi0 + (size_t)r * RS + i), v);
            acc[r] += dot4(ldcs4(wh0 + (size_t)r * RS + i), u);
        }
    }
    block_reduce_sumR<8>(acc, s);
    if (threadIdx.x < 8) {
        int row = row0 + threadIdx.x;
        g_gates[row] = acc[0] + bih[row] + bhh[row];
    }
}

// LSTM cell elementwise; writes h_new/c_new to out and g_hnew
__device__ __forceinline__ float sigm(float v) { return 1.0f / (1.0f + expf(-v)); }
__global__ void __launch_bounds__(256) k_cell(const float* __restrict__ c, float* __restrict__ out) {
    int j = blockIdx.x * blockDim.x + threadIdx.x;
    if (j >= HID) return;
    float ig = g_gates[j];
    float fg = g_gates[HID + j];
    float gg = g_gates[2 * HID + j];
    float og = g_gates[3 * HID + j];
    float cn = sigm(fg) * c[j] + sigm(ig) * tanhf(gg);
    float hn = sigm(og) * tanhf(cn);
    g_hnew[j] = hn;          // earliest visibility for the dependent W_out GEMV
    out[4096 + j] = hn;      // h_new
    out[8192 + j] = cn;      // c_new
}

// log_softmax over 4096 logits -> out[0:4096]
__global__ void __launch_bounds__(1024) k_logsoftmax(float* __restrict__ out) {
    int t = threadIdx.x;                 // 1024 threads, 4 elems each
    float v0 = g_logits[t], v1 = g_logits[t + 1024],
          v2 = g_logits[t + 2048], v3 = g_logits[t + 3072];
    float m = fmaxf(fmaxf(v0, v1), fmaxf(v2, v3));
    __shared__ float sm[32];
    __shared__ float s_max, s_sum;
    int lane = t & 31, wid = t >> 5;
    #pragma unroll
    for (int o = 16; o; o >>= 1) m = fmaxf(m, __shfl_down_sync(0xffffffffu, m, o));
    if (lane == 0) sm[wid] = m;
    __syncthreads();
    if (wid == 0) {
        float v = sm[lane];
        #pragma unroll
        for (int o = 16; o; o >>= 1) v = fmaxf(v, __shfl_down_sync(0xffffffffu, v, o));
        if (lane == 0) s_max = v;
    }
    __syncthreads();
    float mx = s_max;
    float e0 = expf(v0 - mx), e1 = expf(v1 - mx), e2 = expf(v2 - mx), e3 = expf(v3 - mx);
    float ssum = block_reduce_sum(e0 + e1 + e2 + e3);
    if (t == 0) s_sum = ssum;
    __syncthreads();
    float lse = mx + logf(s_sum);
    out[t]        = v0 - lse;
    out[t + 1024] = v1 - lse;
    out[t + 2048] = v2 - lse;
    out[t + 3072] = v3 - lse;
}

// ---------------- launch ----------------------------------------------------
extern "C" void kernel_launch(void* const* d_in, const int* in_sizes, int n_in,
                              void* d_out, int out_size) {
    const int*   token = (const int*)  d_in[0];
    const float* h     = (const float*)d_in[1];
    const float* c     = (const float*)d_in[2];
    const float* enc   = (const float*)d_in[3];
    const float* emb   = (const float*)d_in[4];
    const float* Wattn = (const float*)d_in[5];
    const float* battn = (const float*)d_in[6];
    const float* Wcomb = (const float*)d_in[7];
    const float* bcomb = (const float*)d_in[8];
    const float* Wih   = (const float*)d_in[9];
    const float* Whh   = (const float*)d_in[10];
    const float* bih   = (const float*)d_in[11];
    const float* bhh   = (const float*)d_in[12];
    const float* Wout  = (const float*)d_in[13];
    const float* bout  = (const float*)d_in[14];
    float* out = (float*)d_out;

    float *d_attn_logits, *d_ctx, *d_x, *d_hnew, *d_logits;
    cudaGetSymbolAddress((void**)&d_attn_logits, g_attn_logits);
    cudaGetSymbolAddress((void**)&d_ctx,  g_ctx);
    cudaGetSymbolAddress((void**)&d_x,    g_x);
    cudaGetSymbolAddress((void**)&d_hnew, g_hnew);
    cudaGetSymbolAddress((void**)&d_logits, g_logits);

    // 1) attention logits: W_attn @ [emb[token], h] — ROWS=2 -> 1024 blocks
    k_gemv_cat<0, 2><<<LEN / 2, 256>>>(Wattn, token, emb, h, battn, d_attn_logits);
    // 2) fused softmax + ctx partials (+ attn_w to output tail at 12288)
    k_ctx_partial<<<dim3(4, 128), 256>>>(enc, out + 12288);
    k_ctx_reduce<<<16, 256>>>();
    // 3) x = relu(W_comb @ [emb[token], ctx] + b) — ROWS=4 -> 1024 blocks
    k_gemv_cat<1, 4><<<HID / 4, 256>>>(Wcomb, token, emb, d_ctx, bcomb, d_x);
    // 4) gates = W_ih@x + W_hh@h + b_ih + b_hh — ROWS=8 -> 2048 blocks
    k_gates8<<<4 * HID / 8, 256>>>(Wih, Whh, h, bih, bhh);
    // 5) LSTM cell -> h_new, c_new
    k_cell<<<HID / 256, 256>>>(c, out);
    // 6) logits = W_out @ h_new + b_out — ROWS=4 -> 1024 blocks
    k_gemv<HID, 4><<<VOC / 4, 256>>>(Wout, d_hnew, bout, d_logits);
    // 7) log_softmax -> out[0:4096]
    k_logsoftmax<<<1, 1024>>>(out);
}